// round 15
// baseline (speedup 1.0000x reference)
#include <cuda_runtime.h>
#include <cuda_fp16.h>
#include <math.h>
#include <cstdint>

#define S_LEN 2048
#define HID   2048
#define NH    16
#define NKV   4
#define HD    128
#define BATCH 2
#define MROWS (BATCH * S_LEN)          // 4096

// ---------------- fp16 scratch ----------------
__device__ __half g_x16[(size_t)MROWS * HID];
__device__ __half g_ao16[(size_t)MROWS * HID];
__device__ __half g_q16[(size_t)BATCH * NH  * S_LEN * HD];  // rope applied in place
__device__ __half g_k16[(size_t)BATCH * NKV * S_LEN * HD];  // rope applied in place
__device__ __half g_v16[(size_t)BATCH * NKV * S_LEN * HD];
__device__ __half g_wqs[(size_t)2048 * HID];
__device__ __half g_wks[(size_t)512  * HID];
__device__ __half g_wvs[(size_t)512  * HID];
__device__ __half g_wos[(size_t)2048 * HID];

// ===========================================================================
// Helpers
// ===========================================================================
__device__ __forceinline__ uint32_t smem_u32(const void* p) {
    uint32_t a;
    asm("{ .reg .u64 t; cvta.to.shared.u64 t, %1; cvt.u32.u64 %0, t; }"
        : "=r"(a) : "l"(p));
    return a;
}
__device__ __forceinline__ void ldsm_x4(uint32_t r[4], uint32_t a) {
    asm volatile("ldmatrix.sync.aligned.m8n8.x4.shared.b16 {%0,%1,%2,%3}, [%4];"
                 : "=r"(r[0]), "=r"(r[1]), "=r"(r[2]), "=r"(r[3]) : "r"(a));
}
__device__ __forceinline__ void ldsm_x4_t(uint32_t r[4], uint32_t a) {
    asm volatile("ldmatrix.sync.aligned.m8n8.x4.trans.shared.b16 {%0,%1,%2,%3}, [%4];"
                 : "=r"(r[0]), "=r"(r[1]), "=r"(r[2]), "=r"(r[3]) : "r"(a));
}
__device__ __forceinline__ void mma16816h(float c[4], const uint32_t a[4],
                                          uint32_t b0, uint32_t b1) {
    asm volatile("mma.sync.aligned.m16n8k16.row.col.f32.f16.f16.f32 "
                 "{%0,%1,%2,%3}, {%4,%5,%6,%7}, {%8,%9}, {%0,%1,%2,%3};"
                 : "+f"(c[0]), "+f"(c[1]), "+f"(c[2]), "+f"(c[3])
                 : "r"(a[0]), "r"(a[1]), "r"(a[2]), "r"(a[3]), "r"(b0), "r"(b1));
}
__device__ __forceinline__ uint32_t pack2h(float x0, float x1) {
    uint32_t r;
    asm("cvt.rn.f16x2.f32 %0, %1, %2;" : "=r"(r) : "f"(x1), "f"(x0));
    return r;
}
__device__ __forceinline__ void cp_async16(uint32_t dst, const void* src) {
    asm volatile("cp.async.cg.shared.global [%0], [%1], 16;" :: "r"(dst), "l"(src));
}
#define CP_COMMIT() asm volatile("cp.async.commit_group;" ::: "memory")
#define CP_WAIT(n)  asm volatile("cp.async.wait_group %0;" :: "n"(n) : "memory")

#define SWZ(o) ((o) ^ (((o) >> 3) & 0x70))

// ===========================================================================
// Conversion pass: fp32 -> fp16 (round)
// ===========================================================================
__global__ void round_f32h(const float4* __restrict__ src,
                           uint2* __restrict__ dst, int n4)
{
    int i = blockIdx.x * blockDim.x + threadIdx.x;
    if (i < n4) {
        float4 v = src[i];
        dst[i] = make_uint2(pack2h(v.x, v.y), pack2h(v.z, v.w));
    }
}

// ===========================================================================
// fp16 1-product GEMM (R13 structure — at HMMA roofline)
// 512 threads / 16 warps (8M x 2N), warp tile 16x64, CTA tile 128x128.
// ===========================================================================
#define KCHUNK1 32
#define GSTAGE  32768
#define GEMM_SMEM (2 * GSTAGE)

__device__ __forceinline__ void gemm_tile_1p(
    const __half* __restrict__ A, const __half* __restrict__ B,
    int m0, int n0, float cacc[8][4], char* smem)
{
    int tid = threadIdx.x;
    int warp = tid >> 5, lane = tid & 31;
    int wm = warp >> 1, wn = warp & 1;
    int lr16 = lane & 15, lhalf = (lane >> 4) * 16;
    uint32_t sbase = smem_u32(smem);

    int ar = tid >> 2;
    int aq = (tid & 3) * 32;
    const __half* a0 = A + (size_t)(m0 + ar) * HID + (aq >> 1);
    const __half* b0 = B + (size_t)(n0 + ar) * HID + (aq >> 1);
    uint32_t d0 = SWZ((uint32_t)ar * 128 + aq);
    uint32_t d1 = SWZ((uint32_t)ar * 128 + aq + 16);

#pragma unroll
    for (int ng = 0; ng < 8; ng++)
#pragma unroll
        for (int i = 0; i < 4; i++) cacc[ng][i] = 0.f;

    auto load_stage = [&](int s, int c) {
        uint32_t st = sbase + s * GSTAGE;
        cp_async16(st + d0, a0 + c * 64);
        cp_async16(st + d1, a0 + c * 64 + 8);
        cp_async16(st + 16384 + d0, b0 + c * 64);
        cp_async16(st + 16384 + d1, b0 + c * 64 + 8);
        CP_COMMIT();
    };

    load_stage(0, 0);
    load_stage(1, 1);

    uint32_t arow = (uint32_t)(wm * 16 + lr16) * 128;

    for (int c = 0; c < KCHUNK1; c++) {
        if (c + 1 < KCHUNK1) CP_WAIT(1); else CP_WAIT(0);
        __syncthreads();

        uint32_t abase = sbase + (c & 1) * GSTAGE;
        uint32_t bbase = abase + 16384;

#pragma unroll
        for (int kk = 0; kk < 4; kk++) {
            uint32_t af[4];
            ldsm_x4(af, abase + SWZ(arow + kk * 32 + lhalf));
            uint32_t b0r[8], b1r[8];
#pragma unroll
            for (int t = 0; t < 4; t++) {
                uint32_t r[4];
                ldsm_x4(r, bbase + SWZ((uint32_t)(wn * 64 + t * 16 + lr16) * 128
                                       + kk * 32 + lhalf));
                b0r[2 * t] = r[0]; b0r[2 * t + 1] = r[1];
                b1r[2 * t] = r[2]; b1r[2 * t + 1] = r[3];
            }
#pragma unroll
            for (int ng = 0; ng < 8; ng++)
                mma16816h(cacc[ng], af, b0r[ng], b1r[ng]);
        }
        __syncthreads();
        if (c + 2 < KCHUNK1) load_stage(c & 1, c + 2);
    }
}

// QKV projection. All outputs written directly as fp16 (pre-rope for Q,K).
__global__ void __launch_bounds__(512, 1) gemm_qkv_mma()
{
    extern __shared__ char smem[];
    int nt = blockIdx.x;
    int m0 = blockIdx.y * 128;

    const __half* Bs; __half* dstb; int h, nkvh;
    if (nt < 16)      { Bs = g_wqs; h = nt;      dstb = g_q16; nkvh = NH;  }
    else if (nt < 20) { Bs = g_wks; h = nt - 16; dstb = g_k16; nkvh = NKV; }
    else              { Bs = g_wvs; h = nt - 20; dstb = g_v16; nkvh = NKV; }

    float cacc[8][4];
    gemm_tile_1p(g_x16, Bs, m0, h * HD, cacc, smem);

    int tid = threadIdx.x;
    int warp = tid >> 5, lane = tid & 31;
    int wm = warp >> 1, wn = warp & 1;
    int r0 = lane >> 2, c0 = (lane & 3) * 2;

#pragma unroll
    for (int ng = 0; ng < 8; ng++) {
        int col = wn * 64 + ng * 8 + c0;
#pragma unroll
        for (int half = 0; half < 2; half++) {
            int mg = m0 + wm * 16 + r0 + half * 8;
            int b = mg >> 11, s = mg & (S_LEN - 1);
            __half* d = dstb + ((size_t)(b * nkvh + h) * S_LEN + s) * HD + col;
            *(uint32_t*)d = pack2h(cacc[ng][2 * half], cacc[ng][2 * half + 1]);
        }
    }
}

__global__ void __launch_bounds__(512, 1) gemm_wo_mma(float* __restrict__ out)
{
    extern __shared__ char smem[];
    int n0 = blockIdx.x * 128;
    int m0 = blockIdx.y * 128;

    float cacc[8][4];
    gemm_tile_1p(g_ao16, g_wos, m0, n0, cacc, smem);

    int tid = threadIdx.x;
    int warp = tid >> 5, lane = tid & 31;
    int wm = warp >> 1, wn = warp & 1;
    int r0 = lane >> 2, c0 = (lane & 3) * 2;

#pragma unroll
    for (int ng = 0; ng < 8; ng++) {
        int col = n0 + wn * 64 + ng * 8 + c0;
#pragma unroll
        for (int half = 0; half < 2; half++) {
            int mg = m0 + wm * 16 + r0 + half * 8;
            *(float2*)&out[(size_t)mg * HID + col] =
                make_float2(cacc[ng][2 * half], cacc[ng][2 * half + 1]);
        }
    }
}

// ---------------------------------------------------------------------------
// Fused RoPE for Q and K, fp16 in place (fp32 math). 4 rows/block.
// ---------------------------------------------------------------------------
#define QROWS (BATCH * NH * S_LEN)
#define KROWS (BATCH * NKV * S_LEN)

__global__ void rope_qk16()
{
    int r = blockIdx.x * 4 + (threadIdx.x >> 6);
    int d = threadIdx.x & 63;
    __half* base = (r < QROWS) ? g_q16 + (size_t)r * HD
                               : g_k16 + (size_t)(r - QROWS) * HD;
    int s = r & (S_LEN - 1);
    float inv = (float)exp2(-(double)d * 0.20762050593046747);
    float ang = (float)s * inv;
    float sn, cs;
    sincosf(ang, &sn, &cs);
    float x1 = __half2float(base[d]), x2 = __half2float(base[d + 64]);
    base[d]      = __float2half_rn(x1 * cs - x2 * sn);
    base[d + 64] = __float2half_rn(x1 * sn + x2 * cs);
}

// ===========================================================================
// HMMA flash attention, fp16 1-product both matmuls, all-cp.async operands.
// BM=128 (8 warps x m16), BN=64, 256 threads.
// SMEM: Q 32K (two 16K d-halves) | stage0 [K 16K | V 16K] | stage1 [...]
// scale applied to S after the QK^T MMA.
// ===========================================================================
#define AT_Q  0
#define AT_KV 32768
#define KVSTAGE 32768
#define ATTN_SMEM 98304

__global__ void __launch_bounds__(256, 1) attn_mma(const float* __restrict__ kw)
{
    extern __shared__ char smem[];
    uint32_t sb = smem_u32(smem);

    int tid = threadIdx.x;
    int wq = tid >> 5, lane = tid & 31;
    int lr16 = lane & 15;
    int lhalf = (lane >> 4) * 16;

    int mt = blockIdx.x, h = blockIdx.y, b = blockIdx.z;
    int m0 = mt * 128;
    int kh = h >> 2;
    float scale = kw[h] * 0.08838834764831845f;

    size_t qrow0 = (size_t)(b * NH + h) * S_LEN + m0;
    size_t kvrow0 = (size_t)(b * NKV + kh) * S_LEN;

    // ---- Q via cp.async (first commit group) ----
    {
        int row = tid >> 1;
        int half = tid & 1;
        const __half* src = g_q16 + (qrow0 + row) * HD + half * 64;
        uint32_t qs = sb + AT_Q + half * 16384;
#pragma unroll
        for (int j = 0; j < 8; j++)
            cp_async16(qs + SWZ((uint32_t)row * 128 + j * 16), src + j * 8);
        CP_COMMIT();
    }

    // ---- KV cp.async mapping ----
    int krow = tid >> 2;
    int kd = (tid & 3) * 32;
    const __half* kbase_g = g_k16 + (kvrow0 + krow) * HD + kd;
    const __half* vbase_g = g_v16 + (kvrow0 + krow) * HD + kd;
    uint32_t kvoff[4];
#pragma unroll
    for (int j = 0; j < 4; j++) {
        int d = kd + j * 8;
        kvoff[j] = (uint32_t)(d >> 6) * 8192 + SWZ((uint32_t)krow * 128 + (d & 63) * 2);
    }
    auto load_kv = [&](int s, int nt) {
        uint32_t st = sb + AT_KV + s * KVSTAGE;
        const __half* kp = kbase_g + (size_t)nt * 64 * HD;
        const __half* vp = vbase_g + (size_t)nt * 64 * HD;
#pragma unroll
        for (int j = 0; j < 4; j++) {
            cp_async16(st + kvoff[j], kp + j * 8);
            cp_async16(st + 16384 + kvoff[j], vp + j * 8);
        }
        CP_COMMIT();
    };

    int ntiles = 2 * mt + 2;
    load_kv(0, 0);
    load_kv(1, 1);

    float m1 = -1e30f, m2 = -1e30f, l1s = 0.f, l2s = 0.f;
    float oacc[16][4];
#pragma unroll
    for (int ng = 0; ng < 16; ng++)
#pragma unroll
        for (int i = 0; i < 4; i++) oacc[ng][i] = 0.f;

    int vrow_off = (lane & 7) + ((lane >> 3) & 1) * 8;
    int vcol8 = (lane >> 4) * 8;

    for (int nt = 0; nt < ntiles; nt++) {
        int n0 = nt * 64;
        // groups pending: Q (first iter only), kv tiles. wait(1) leaves at most
        // the newest kv group outstanding; Q + current kv are complete.
        if (nt + 1 < ntiles) CP_WAIT(1); else CP_WAIT(0);
        __syncthreads();

        uint32_t kstage = sb + AT_KV + (nt & 1) * KVSTAGE;
        uint32_t vstage = kstage + 16384;

        // ---- S = Q K^T (1 product) ----
        float sacc[8][4];
#pragma unroll
        for (int ng = 0; ng < 8; ng++)
#pragma unroll
            for (int i = 0; i < 4; i++) sacc[ng][i] = 0.f;

#pragma unroll
        for (int ks = 0; ks < 8; ks++) {
            int half = ks >> 2;
            uint32_t koff = (ks & 3) * 32 + lhalf;
            uint32_t af[4];
            ldsm_x4(af, sb + AT_Q + half * 16384
                        + SWZ((uint32_t)(wq * 16 + lr16) * 128 + koff));
            uint32_t b0[8], b1[8];
#pragma unroll
            for (int t = 0; t < 4; t++) {
                uint32_t r[4];
                ldsm_x4(r, kstage + half * 8192
                           + SWZ((uint32_t)(t * 16 + lr16) * 128 + koff));
                b0[2 * t] = r[0]; b0[2 * t + 1] = r[1];
                b1[2 * t] = r[2]; b1[2 * t + 1] = r[3];
            }
#pragma unroll
            for (int ng = 0; ng < 8; ng++)
                mma16816h(sacc[ng], af, b0[ng], b1[ng]);
        }

        // ---- apply scale (post-MMA, algebraically identical) ----
#pragma unroll
        for (int ng = 0; ng < 8; ng++)
#pragma unroll
            for (int i = 0; i < 4; i++) sacc[ng][i] *= scale;

        // ---- causal mask (last two tiles only) ----
        if (nt >= 2 * mt) {
            int rg1 = m0 + wq * 16 + (lane >> 2);
            int rg2 = rg1 + 8;
            int cb = n0 + (lane & 3) * 2;
#pragma unroll
            for (int ng = 0; ng < 8; ng++) {
                int c0g = cb + ng * 8;
                if (c0g > rg1)     sacc[ng][0] = -1e30f;
                if (c0g + 1 > rg1) sacc[ng][1] = -1e30f;
                if (c0g > rg2)     sacc[ng][2] = -1e30f;
                if (c0g + 1 > rg2) sacc[ng][3] = -1e30f;
            }
        }

        // ---- online softmax ----
        float rmax1 = -1e30f, rmax2 = -1e30f;
#pragma unroll
        for (int ng = 0; ng < 8; ng++) {
            rmax1 = fmaxf(rmax1, fmaxf(sacc[ng][0], sacc[ng][1]));
            rmax2 = fmaxf(rmax2, fmaxf(sacc[ng][2], sacc[ng][3]));
        }
        rmax1 = fmaxf(rmax1, __shfl_xor_sync(0xffffffffu, rmax1, 1));
        rmax1 = fmaxf(rmax1, __shfl_xor_sync(0xffffffffu, rmax1, 2));
        rmax2 = fmaxf(rmax2, __shfl_xor_sync(0xffffffffu, rmax2, 1));
        rmax2 = fmaxf(rmax2, __shfl_xor_sync(0xffffffffu, rmax2, 2));

        float mn1 = fmaxf(m1, rmax1);
        float mn2 = fmaxf(m2, rmax2);
        float alpha1 = __expf(m1 - mn1);
        float alpha2 = __expf(m2 - mn2);
        m1 = mn1; m2 = mn2;

        float rsum1 = 0.f, rsum2 = 0.f;
#pragma unroll
        for (int ng = 0; ng < 8; ng++) {
            sacc[ng][0] = __expf(sacc[ng][0] - mn1);
            sacc[ng][1] = __expf(sacc[ng][1] - mn1);
            sacc[ng][2] = __expf(sacc[ng][2] - mn2);
            sacc[ng][3] = __expf(sacc[ng][3] - mn2);
            rsum1 += sacc[ng][0] + sacc[ng][1];
            rsum2 += sacc[ng][2] + sacc[ng][3];
        }
        rsum1 += __shfl_xor_sync(0xffffffffu, rsum1, 1);
        rsum1 += __shfl_xor_sync(0xffffffffu, rsum1, 2);
        rsum2 += __shfl_xor_sync(0xffffffffu, rsum2, 1);
        rsum2 += __shfl_xor_sync(0xffffffffu, rsum2, 2);
        l1s = l1s * alpha1 + rsum1;
        l2s = l2s * alpha2 + rsum2;

#pragma unroll
        for (int ng = 0; ng < 16; ng++) {
            oacc[ng][0] *= alpha1; oacc[ng][1] *= alpha1;
            oacc[ng][2] *= alpha2; oacc[ng][3] *= alpha2;
        }

        // ---- O += P V (1 product; P rounded to fp16 in registers) ----
#pragma unroll
        for (int ks = 0; ks < 4; ks++) {
            uint32_t pha[4];
            pha[0] = pack2h(sacc[2 * ks][0],     sacc[2 * ks][1]);
            pha[1] = pack2h(sacc[2 * ks][2],     sacc[2 * ks][3]);
            pha[2] = pack2h(sacc[2 * ks + 1][0], sacc[2 * ks + 1][1]);
            pha[3] = pack2h(sacc[2 * ks + 1][2], sacc[2 * ks + 1][3]);

            uint32_t vrow = (uint32_t)(ks * 16 + vrow_off) * 128;
#pragma unroll
            for (int t = 0; t < 8; t++) {
                int half = t >> 2;
                uint32_t coff = ((t & 3) * 16 + vcol8) * 2;
                uint32_t r[4];
                ldsm_x4_t(r, vstage + half * 8192 + SWZ(vrow + coff));
                mma16816h(oacc[2 * t],     pha, r[0], r[1]);
                mma16816h(oacc[2 * t + 1], pha, r[2], r[3]);
            }
        }

        __syncthreads();
        if (nt + 2 < ntiles) load_kv(nt & 1, nt + 2);
    }

    // ---- epilogue: normalize, write single fp16 plane for WO GEMM ----
    float inv1 = 1.0f / l1s;
    float inv2 = 1.0f / l2s;
    int r1 = m0 + wq * 16 + (lane >> 2);
    int c0 = (lane & 3) * 2;
    size_t base1 = ((size_t)(b * S_LEN + r1)) * HID + h * HD;
    size_t base2 = ((size_t)(b * S_LEN + r1 + 8)) * HID + h * HD;
#pragma unroll
    for (int ng = 0; ng < 16; ng++) {
        int d = ng * 8 + c0;
        *(uint32_t*)&g_ao16[base1 + d] = pack2h(oacc[ng][0] * inv1, oacc[ng][1] * inv1);
        *(uint32_t*)&g_ao16[base2 + d] = pack2h(oacc[ng][2] * inv2, oacc[ng][3] * inv2);
    }
}

// ---------------------------------------------------------------------------
// Launch
// ---------------------------------------------------------------------------
extern "C" void kernel_launch(void* const* d_in, const int* in_sizes, int n_in,
                              void* d_out, int out_size)
{
    const float* x  = (const float*)d_in[0];
    const float* wq = (const float*)d_in[1];
    const float* wk = (const float*)d_in[2];
    const float* wv = (const float*)d_in[3];
    const float* wo = (const float*)d_in[4];
    const float* kw = (const float*)d_in[5];
    float* out = (float*)d_out;

    cudaFuncSetAttribute(attn_mma, cudaFuncAttributeMaxDynamicSharedMemorySize,
                         ATTN_SMEM);
    cudaFuncSetAttribute(gemm_qkv_mma, cudaFuncAttributeMaxDynamicSharedMemorySize,
                         GEMM_SMEM);
    cudaFuncSetAttribute(gemm_wo_mma, cudaFuncAttributeMaxDynamicSharedMemorySize,
                         GEMM_SMEM);

    void *x16, *wqs, *wks, *wvs, *wos;
    cudaGetSymbolAddress(&x16, g_x16);
    cudaGetSymbolAddress(&wqs, g_wqs); cudaGetSymbolAddress(&wks, g_wks);
    cudaGetSymbolAddress(&wvs, g_wvs); cudaGetSymbolAddress(&wos, g_wos);

    auto roundh = [&](const float* src, void* dst, size_t n) {
        int n4 = (int)(n / 4);
        round_f32h<<<(n4 + 255) / 256, 256>>>((const float4*)src, (uint2*)dst, n4);
    };

    // round inputs to single fp16 planes
    roundh(x,  x16, (size_t)MROWS * HID);
    roundh(wq, wqs, (size_t)2048 * HID);
    roundh(wk, wks, (size_t)512 * HID);
    roundh(wv, wvs, (size_t)512 * HID);
    roundh(wo, wos, (size_t)2048 * HID);

    // QKV projection (fp16 1-product; Q/K/V all written as fp16)
    gemm_qkv_mma<<<dim3(24, 32), 512, GEMM_SMEM>>>();

    // Fused RoPE on Q and K (fp16 in place)
    rope_qk16<<<(QROWS + KROWS) / 4, 256>>>();

    // Attention (fp16 1-product; fully cp.async operands; writes fp16 g_ao16)
    attn_mma<<<dim3(S_LEN / 128, NH, BATCH), 256, ATTN_SMEM>>>(kw);

    // Output projection (fp16 1-product)
    gemm_wo_mma<<<dim3(16, 32), 512, GEMM_SMEM>>>(out);
}

// round 16
// speedup vs baseline: 1.0521x; 1.0521x over previous
#include <cuda_runtime.h>
#include <cuda_fp16.h>
#include <math.h>
#include <cstdint>

#define S_LEN 2048
#define HID   2048
#define NH    16
#define NKV   4
#define HD    128
#define BATCH 2
#define MROWS (BATCH * S_LEN)          // 4096

// ---------------- fp32 scratch ----------------
__device__ float g_q[(size_t)BATCH * NH  * S_LEN * HD];   // [b][h][s][d]
__device__ float g_k[(size_t)BATCH * NKV * S_LEN * HD];   // pre-rope

// ---------------- fp16 scratch ----------------
__device__ __half g_x16[(size_t)MROWS * HID];
__device__ __half g_ao16[(size_t)MROWS * HID];
__device__ __half g_k16[(size_t)BATCH * NKV * S_LEN * HD];  // post-rope
__device__ __half g_v16[(size_t)BATCH * NKV * S_LEN * HD];  // written by QKV GEMM
__device__ __half g_wqs[(size_t)2048 * HID];
__device__ __half g_wks[(size_t)512  * HID];
__device__ __half g_wvs[(size_t)512  * HID];
__device__ __half g_wos[(size_t)2048 * HID];

// ===========================================================================
// Helpers
// ===========================================================================
__device__ __forceinline__ uint32_t smem_u32(const void* p) {
    uint32_t a;
    asm("{ .reg .u64 t; cvta.to.shared.u64 t, %1; cvt.u32.u64 %0, t; }"
        : "=r"(a) : "l"(p));
    return a;
}
__device__ __forceinline__ void ldsm_x4(uint32_t r[4], uint32_t a) {
    asm volatile("ldmatrix.sync.aligned.m8n8.x4.shared.b16 {%0,%1,%2,%3}, [%4];"
                 : "=r"(r[0]), "=r"(r[1]), "=r"(r[2]), "=r"(r[3]) : "r"(a));
}
__device__ __forceinline__ void ldsm_x4_t(uint32_t r[4], uint32_t a) {
    asm volatile("ldmatrix.sync.aligned.m8n8.x4.trans.shared.b16 {%0,%1,%2,%3}, [%4];"
                 : "=r"(r[0]), "=r"(r[1]), "=r"(r[2]), "=r"(r[3]) : "r"(a));
}
__device__ __forceinline__ void mma16816h(float c[4], const uint32_t a[4],
                                          uint32_t b0, uint32_t b1) {
    asm volatile("mma.sync.aligned.m16n8k16.row.col.f32.f16.f16.f32 "
                 "{%0,%1,%2,%3}, {%4,%5,%6,%7}, {%8,%9}, {%0,%1,%2,%3};"
                 : "+f"(c[0]), "+f"(c[1]), "+f"(c[2]), "+f"(c[3])
                 : "r"(a[0]), "r"(a[1]), "r"(a[2]), "r"(a[3]), "r"(b0), "r"(b1));
}
__device__ __forceinline__ uint32_t pack2h(float x0, float x1) {
    uint32_t r;
    asm("cvt.rn.f16x2.f32 %0, %1, %2;" : "=r"(r) : "f"(x1), "f"(x0));
    return r;
}
__device__ __forceinline__ void cp_async16(uint32_t dst, const void* src) {
    asm volatile("cp.async.cg.shared.global [%0], [%1], 16;" :: "r"(dst), "l"(src));
}
#define CP_COMMIT() asm volatile("cp.async.commit_group;" ::: "memory")
#define CP_WAIT(n)  asm volatile("cp.async.wait_group %0;" :: "n"(n) : "memory")

#define SWZ(o) ((o) ^ (((o) >> 3) & 0x70))

// ===========================================================================
// Fused rounding pass: all five tensors in one launch.
// Regions (in float4 units): x | wq | wk | wv | wo
// ===========================================================================
#define N4_X  (MROWS * HID / 4)          // 2097152
#define N4_WQ (2048 * HID / 4)           // 1048576
#define N4_WK (512 * HID / 4)            // 262144
#define N4_WV N4_WK
#define N4_WO N4_WQ
#define N4_ALL (N4_X + N4_WQ + N4_WK + N4_WV + N4_WO)

__global__ void round_all(const float4* __restrict__ x,  const float4* __restrict__ wq,
                          const float4* __restrict__ wk, const float4* __restrict__ wv,
                          const float4* __restrict__ wo)
{
    int i = blockIdx.x * blockDim.x + threadIdx.x;
    if (i >= N4_ALL) return;
    const float4* src; uint2* dst; int j = i;
    if (j < N4_X)                  { src = x;  dst = (uint2*)g_x16; }
    else if ((j -= N4_X)  < N4_WQ) { src = wq; dst = (uint2*)g_wqs; }
    else if ((j -= N4_WQ) < N4_WK) { src = wk; dst = (uint2*)g_wks; }
    else if ((j -= N4_WK) < N4_WV) { src = wv; dst = (uint2*)g_wvs; }
    else { j -= N4_WV;               src = wo; dst = (uint2*)g_wos; }
    float4 v = src[j];
    dst[j] = make_uint2(pack2h(v.x, v.y), pack2h(v.z, v.w));
}

// ===========================================================================
// fp16 1-product GEMM (R13/R14 verbatim — at HMMA roofline)
// 512 threads / 16 warps (8M x 2N), warp tile 16x64, CTA tile 128x128.
// ===========================================================================
#define KCHUNK1 32
#define GSTAGE  32768
#define GEMM_SMEM (2 * GSTAGE)

__device__ __forceinline__ void gemm_tile_1p(
    const __half* __restrict__ A, const __half* __restrict__ B,
    int m0, int n0, float cacc[8][4], char* smem)
{
    int tid = threadIdx.x;
    int warp = tid >> 5, lane = tid & 31;
    int wm = warp >> 1, wn = warp & 1;
    int lr16 = lane & 15, lhalf = (lane >> 4) * 16;
    uint32_t sbase = smem_u32(smem);

    int ar = tid >> 2;
    int aq = (tid & 3) * 32;
    const __half* a0 = A + (size_t)(m0 + ar) * HID + (aq >> 1);
    const __half* b0 = B + (size_t)(n0 + ar) * HID + (aq >> 1);
    uint32_t d0 = SWZ((uint32_t)ar * 128 + aq);
    uint32_t d1 = SWZ((uint32_t)ar * 128 + aq + 16);

#pragma unroll
    for (int ng = 0; ng < 8; ng++)
#pragma unroll
        for (int i = 0; i < 4; i++) cacc[ng][i] = 0.f;

    auto load_stage = [&](int s, int c) {
        uint32_t st = sbase + s * GSTAGE;
        cp_async16(st + d0, a0 + c * 64);
        cp_async16(st + d1, a0 + c * 64 + 8);
        cp_async16(st + 16384 + d0, b0 + c * 64);
        cp_async16(st + 16384 + d1, b0 + c * 64 + 8);
        CP_COMMIT();
    };

    load_stage(0, 0);
    load_stage(1, 1);

    uint32_t arow = (uint32_t)(wm * 16 + lr16) * 128;

    for (int c = 0; c < KCHUNK1; c++) {
        if (c + 1 < KCHUNK1) CP_WAIT(1); else CP_WAIT(0);
        __syncthreads();

        uint32_t abase = sbase + (c & 1) * GSTAGE;
        uint32_t bbase = abase + 16384;

#pragma unroll
        for (int kk = 0; kk < 4; kk++) {
            uint32_t af[4];
            ldsm_x4(af, abase + SWZ(arow + kk * 32 + lhalf));
            uint32_t b0r[8], b1r[8];
#pragma unroll
            for (int t = 0; t < 4; t++) {
                uint32_t r[4];
                ldsm_x4(r, bbase + SWZ((uint32_t)(wn * 64 + t * 16 + lr16) * 128
                                       + kk * 32 + lhalf));
                b0r[2 * t] = r[0]; b0r[2 * t + 1] = r[1];
                b1r[2 * t] = r[2]; b1r[2 * t + 1] = r[3];
            }
#pragma unroll
            for (int ng = 0; ng < 8; ng++)
                mma16816h(cacc[ng], af, b0r[ng], b1r[ng]);
        }
        __syncthreads();
        if (c + 2 < KCHUNK1) load_stage(c & 1, c + 2);
    }
}

// QKV projection. nt<16: Q (fp32 out), 16..19: K (fp32 out), 20..23: V (fp16 out).
__global__ void __launch_bounds__(512, 1) gemm_qkv_mma()
{
    extern __shared__ char smem[];
    int nt = blockIdx.x;
    int m0 = blockIdx.y * 128;

    const __half* Bs; int h, kind;   // kind: 0=Q, 1=K, 2=V
    if (nt < 16)      { Bs = g_wqs; h = nt;      kind = 0; }
    else if (nt < 20) { Bs = g_wks; h = nt - 16; kind = 1; }
    else              { Bs = g_wvs; h = nt - 20; kind = 2; }

    float cacc[8][4];
    gemm_tile_1p(g_x16, Bs, m0, h * HD, cacc, smem);

    int tid = threadIdx.x;
    int warp = tid >> 5, lane = tid & 31;
    int wm = warp >> 1, wn = warp & 1;
    int r0 = lane >> 2, c0 = (lane & 3) * 2;

#pragma unroll
    for (int ng = 0; ng < 8; ng++) {
        int col = wn * 64 + ng * 8 + c0;
#pragma unroll
        for (int half = 0; half < 2; half++) {
            int mg = m0 + wm * 16 + r0 + half * 8;
            int b = mg >> 11, s = mg & (S_LEN - 1);
            float v0 = cacc[ng][2 * half], v1 = cacc[ng][2 * half + 1];
            if (kind == 0) {
                float* d = g_q + ((size_t)(b * NH + h) * S_LEN + s) * HD + col;
                *(float2*)d = make_float2(v0, v1);
            } else if (kind == 1) {
                float* d = g_k + ((size_t)(b * NKV + h) * S_LEN + s) * HD + col;
                *(float2*)d = make_float2(v0, v1);
            } else {
                __half* d = g_v16 + ((size_t)(b * NKV + h) * S_LEN + s) * HD + col;
                *(uint32_t*)d = pack2h(v0, v1);
            }
        }
    }
}

__global__ void __launch_bounds__(512, 1) gemm_wo_mma(float* __restrict__ out)
{
    extern __shared__ char smem[];
    int n0 = blockIdx.x * 128;
    int m0 = blockIdx.y * 128;

    float cacc[8][4];
    gemm_tile_1p(g_ao16, g_wos, m0, n0, cacc, smem);

    int tid = threadIdx.x;
    int warp = tid >> 5, lane = tid & 31;
    int wm = warp >> 1, wn = warp & 1;
    int r0 = lane >> 2, c0 = (lane & 3) * 2;

#pragma unroll
    for (int ng = 0; ng < 8; ng++) {
        int col = n0 + wn * 64 + ng * 8 + c0;
#pragma unroll
        for (int half = 0; half < 2; half++) {
            int mg = m0 + wm * 16 + r0 + half * 8;
            *(float2*)&out[(size_t)mg * HID + col] =
                make_float2(cacc[ng][2 * half], cacc[ng][2 * half + 1]);
        }
    }
}

// ---------------------------------------------------------------------------
// Fused RoPE: Q fp32 in-place; K fp32 -> fp16. 4 rows/block, one launch.
// ---------------------------------------------------------------------------
#define QROWS (BATCH * NH * S_LEN)
#define KROWS (BATCH * NKV * S_LEN)

__global__ void rope_fused()
{
    int r = blockIdx.x * 4 + (threadIdx.x >> 6);
    int d = threadIdx.x & 63;
    int s = r & (S_LEN - 1);
    float inv = (float)exp2(-(double)d * 0.20762050593046747);
    float ang = (float)s * inv;
    float sn, cs;
    sincosf(ang, &sn, &cs);
    if (r < QROWS) {
        float* base = g_q + (size_t)r * HD;
        float x1 = base[d], x2 = base[d + 64];
        base[d]      = x1 * cs - x2 * sn;
        base[d + 64] = x1 * sn + x2 * cs;
    } else {
        size_t rk = (size_t)(r - QROWS);
        const float* base = g_k + rk * HD;
        float x1 = base[d], x2 = base[d + 64];
        g_k16[rk * HD + d]      = __float2half_rn(x1 * cs - x2 * sn);
        g_k16[rk * HD + d + 64] = __float2half_rn(x1 * sn + x2 * cs);
    }
}

// ===========================================================================
// HMMA flash attention (R14 verbatim + reversed mt mapping for load balance).
// fp16 1-product both matmuls. BM=128, BN=64, 256 threads.
// SMEM: Q 32K (two 16K d-halves) | stage0 [K 16K | V 16K] | stage1 [...]
// ===========================================================================
#define AT_Q  0
#define AT_KV 32768
#define KVSTAGE 32768
#define ATTN_SMEM 98304

__global__ void __launch_bounds__(256, 1) attn_mma(const float* __restrict__ kw)
{
    extern __shared__ char smem[];
    uint32_t sb = smem_u32(smem);

    int tid = threadIdx.x;
    int wq = tid >> 5, lane = tid & 31;
    int lr16 = lane & 15;
    int lhalf = (lane >> 4) * 16;

    // heavy tiles (large mt) first: better last-wave balance
    int mt = (int)gridDim.x - 1 - (int)blockIdx.x;
    int h = blockIdx.y, b = blockIdx.z;
    int m0 = mt * 128;
    int kh = h >> 2;
    float scale = kw[h] * 0.08838834764831845f;

    const float* qg = g_q + ((size_t)(b * NH + h) * S_LEN + m0) * HD;
    size_t kvrow0 = (size_t)(b * NKV + kh) * S_LEN;

    int krow = tid >> 2;
    int kd = (tid & 3) * 32;
    const __half* kbase_g = g_k16 + (kvrow0 + krow) * HD + kd;
    const __half* vbase_g = g_v16 + (kvrow0 + krow) * HD + kd;
    uint32_t kvoff[4];
#pragma unroll
    for (int j = 0; j < 4; j++) {
        int d = kd + j * 8;
        kvoff[j] = (uint32_t)(d >> 6) * 8192 + SWZ((uint32_t)krow * 128 + (d & 63) * 2);
    }
    auto load_kv = [&](int s, int nt) {
        uint32_t st = sb + AT_KV + s * KVSTAGE;
        const __half* kp = kbase_g + (size_t)nt * 64 * HD;
        const __half* vp = vbase_g + (size_t)nt * 64 * HD;
#pragma unroll
        for (int j = 0; j < 4; j++) {
            cp_async16(st + kvoff[j], kp + j * 8);
            cp_async16(st + 16384 + kvoff[j], vp + j * 8);
        }
        CP_COMMIT();
    };

    int ntiles = 2 * mt + 2;
    load_kv(0, 0);
    load_kv(1, 1);

    // ---- load + scale + round Q (single fp16 plane) ----
    {
        int row = tid >> 1;
        int dst = (tid & 1) * 64;
        const float* src = qg + (size_t)row * HD + dst;
        char* qp = smem + AT_Q + (dst >> 6) * 16384;
#pragma unroll
        for (int j = 0; j < 16; j++) {
            float4 v = *(const float4*)(src + j * 4);
            uint32_t p0 = pack2h(v.x * scale, v.y * scale);
            uint32_t p1 = pack2h(v.z * scale, v.w * scale);
            uint32_t off = (uint32_t)row * 128 + ((dst + j * 4) & 63) * 2;
            *(uint2*)(qp + SWZ(off)) = make_uint2(p0, p1);
        }
    }

    float m1 = -1e30f, m2 = -1e30f, l1s = 0.f, l2s = 0.f;
    float oacc[16][4];
#pragma unroll
    for (int ng = 0; ng < 16; ng++)
#pragma unroll
        for (int i = 0; i < 4; i++) oacc[ng][i] = 0.f;

    int vrow_off = (lane & 7) + ((lane >> 3) & 1) * 8;
    int vcol8 = (lane >> 4) * 8;

    for (int nt = 0; nt < ntiles; nt++) {
        int n0 = nt * 64;
        if (nt + 1 < ntiles) CP_WAIT(1); else CP_WAIT(0);
        __syncthreads();

        uint32_t kstage = sb + AT_KV + (nt & 1) * KVSTAGE;
        uint32_t vstage = kstage + 16384;

        // ---- S = Q K^T (1 product) ----
        float sacc[8][4];
#pragma unroll
        for (int ng = 0; ng < 8; ng++)
#pragma unroll
            for (int i = 0; i < 4; i++) sacc[ng][i] = 0.f;

#pragma unroll
        for (int ks = 0; ks < 8; ks++) {
            int half = ks >> 2;
            uint32_t koff = (ks & 3) * 32 + lhalf;
            uint32_t af[4];
            ldsm_x4(af, sb + AT_Q + half * 16384
                        + SWZ((uint32_t)(wq * 16 + lr16) * 128 + koff));
            uint32_t b0[8], b1[8];
#pragma unroll
            for (int t = 0; t < 4; t++) {
                uint32_t r[4];
                ldsm_x4(r, kstage + half * 8192
                           + SWZ((uint32_t)(t * 16 + lr16) * 128 + koff));
                b0[2 * t] = r[0]; b0[2 * t + 1] = r[1];
                b1[2 * t] = r[2]; b1[2 * t + 1] = r[3];
            }
#pragma unroll
            for (int ng = 0; ng < 8; ng++)
                mma16816h(sacc[ng], af, b0[ng], b1[ng]);
        }

        // ---- causal mask (last two tiles only) ----
        if (nt >= 2 * mt) {
            int rg1 = m0 + wq * 16 + (lane >> 2);
            int rg2 = rg1 + 8;
            int cb = n0 + (lane & 3) * 2;
#pragma unroll
            for (int ng = 0; ng < 8; ng++) {
                int c0g = cb + ng * 8;
                if (c0g > rg1)     sacc[ng][0] = -1e30f;
                if (c0g + 1 > rg1) sacc[ng][1] = -1e30f;
                if (c0g > rg2)     sacc[ng][2] = -1e30f;
                if (c0g + 1 > rg2) sacc[ng][3] = -1e30f;
            }
        }

        // ---- online softmax ----
        float rmax1 = -1e30f, rmax2 = -1e30f;
#pragma unroll
        for (int ng = 0; ng < 8; ng++) {
            rmax1 = fmaxf(rmax1, fmaxf(sacc[ng][0], sacc[ng][1]));
            rmax2 = fmaxf(rmax2, fmaxf(sacc[ng][2], sacc[ng][3]));
        }
        rmax1 = fmaxf(rmax1, __shfl_xor_sync(0xffffffffu, rmax1, 1));
        rmax1 = fmaxf(rmax1, __shfl_xor_sync(0xffffffffu, rmax1, 2));
        rmax2 = fmaxf(rmax2, __shfl_xor_sync(0xffffffffu, rmax2, 1));
        rmax2 = fmaxf(rmax2, __shfl_xor_sync(0xffffffffu, rmax2, 2));

        float mn1 = fmaxf(m1, rmax1);
        float mn2 = fmaxf(m2, rmax2);
        float alpha1 = __expf(m1 - mn1);
        float alpha2 = __expf(m2 - mn2);
        m1 = mn1; m2 = mn2;

        float rsum1 = 0.f, rsum2 = 0.f;
#pragma unroll
        for (int ng = 0; ng < 8; ng++) {
            sacc[ng][0] = __expf(sacc[ng][0] - mn1);
            sacc[ng][1] = __expf(sacc[ng][1] - mn1);
            sacc[ng][2] = __expf(sacc[ng][2] - mn2);
            sacc[ng][3] = __expf(sacc[ng][3] - mn2);
            rsum1 += sacc[ng][0] + sacc[ng][1];
            rsum2 += sacc[ng][2] + sacc[ng][3];
        }
        rsum1 += __shfl_xor_sync(0xffffffffu, rsum1, 1);
        rsum1 += __shfl_xor_sync(0xffffffffu, rsum1, 2);
        rsum2 += __shfl_xor_sync(0xffffffffu, rsum2, 1);
        rsum2 += __shfl_xor_sync(0xffffffffu, rsum2, 2);
        l1s = l1s * alpha1 + rsum1;
        l2s = l2s * alpha2 + rsum2;

#pragma unroll
        for (int ng = 0; ng < 16; ng++) {
            oacc[ng][0] *= alpha1; oacc[ng][1] *= alpha1;
            oacc[ng][2] *= alpha2; oacc[ng][3] *= alpha2;
        }

        // ---- O += P V (1 product; P rounded to fp16 in registers) ----
#pragma unroll
        for (int ks = 0; ks < 4; ks++) {
            uint32_t pha[4];
            pha[0] = pack2h(sacc[2 * ks][0],     sacc[2 * ks][1]);
            pha[1] = pack2h(sacc[2 * ks][2],     sacc[2 * ks][3]);
            pha[2] = pack2h(sacc[2 * ks + 1][0], sacc[2 * ks + 1][1]);
            pha[3] = pack2h(sacc[2 * ks + 1][2], sacc[2 * ks + 1][3]);

            uint32_t vrow = (uint32_t)(ks * 16 + vrow_off) * 128;
#pragma unroll
            for (int t = 0; t < 8; t++) {
                int half = t >> 2;
                uint32_t coff = ((t & 3) * 16 + vcol8) * 2;
                uint32_t r[4];
                ldsm_x4_t(r, vstage + half * 8192 + SWZ(vrow + coff));
                mma16816h(oacc[2 * t],     pha, r[0], r[1]);
                mma16816h(oacc[2 * t + 1], pha, r[2], r[3]);
            }
        }

        __syncthreads();
        if (nt + 2 < ntiles) load_kv(nt & 1, nt + 2);
    }

    // ---- epilogue: normalize, write single fp16 plane for WO GEMM ----
    float inv1 = 1.0f / l1s;
    float inv2 = 1.0f / l2s;
    int r1 = m0 + wq * 16 + (lane >> 2);
    int c0 = (lane & 3) * 2;
    size_t base1 = ((size_t)(b * S_LEN + r1)) * HID + h * HD;
    size_t base2 = ((size_t)(b * S_LEN + r1 + 8)) * HID + h * HD;
#pragma unroll
    for (int ng = 0; ng < 16; ng++) {
        int d = ng * 8 + c0;
        *(uint32_t*)&g_ao16[base1 + d] = pack2h(oacc[ng][0] * inv1, oacc[ng][1] * inv1);
        *(uint32_t*)&g_ao16[base2 + d] = pack2h(oacc[ng][2] * inv2, oacc[ng][3] * inv2);
    }
}

// ---------------------------------------------------------------------------
// Launch
// ---------------------------------------------------------------------------
extern "C" void kernel_launch(void* const* d_in, const int* in_sizes, int n_in,
                              void* d_out, int out_size)
{
    const float* x  = (const float*)d_in[0];
    const float* wq = (const float*)d_in[1];
    const float* wk = (const float*)d_in[2];
    const float* wv = (const float*)d_in[3];
    const float* wo = (const float*)d_in[4];
    const float* kw = (const float*)d_in[5];
    float* out = (float*)d_out;

    cudaFuncSetAttribute(attn_mma, cudaFuncAttributeMaxDynamicSharedMemorySize,
                         ATTN_SMEM);
    cudaFuncSetAttribute(gemm_qkv_mma, cudaFuncAttributeMaxDynamicSharedMemorySize,
                         GEMM_SMEM);
    cudaFuncSetAttribute(gemm_wo_mma, cudaFuncAttributeMaxDynamicSharedMemorySize,
                         GEMM_SMEM);

    // one fused rounding pass for all five input tensors
    round_all<<<(N4_ALL + 255) / 256, 256>>>((const float4*)x, (const float4*)wq,
                                             (const float4*)wk, (const float4*)wv,
                                             (const float4*)wo);

    // QKV projection (fp16 1-product; V written directly as fp16)
    gemm_qkv_mma<<<dim3(24, 32), 512, GEMM_SMEM>>>();

    // fused RoPE: Q fp32 in-place + K fp32->fp16, single launch
    rope_fused<<<(QROWS + KROWS) / 4, 256>>>();

    // Attention (fp16 1-product; heavy-mt-first mapping; writes fp16 g_ao16)
    attn_mma<<<dim3(S_LEN / 128, NH, BATCH), 256, ATTN_SMEM>>>(kw);

    // Output projection (fp16 1-product)
    gemm_wo_mma<<<dim3(16, 32), 512, GEMM_SMEM>>>(out);
}